// round 13
// baseline (speedup 1.0000x reference)
#include <cuda_runtime.h>
#include <cuda_fp16.h>
#include <cstdint>

#define NN 50000
#define NE 640000
#define PSTR 72

// ============================= device scratch =============================
__device__ __align__(16) float g_agg[(size_t)NN * 128];   // mean of edge messages
__device__ int   g_is64;
__device__ int   g_icnt[NN];        // per-node edge count (int)
__device__ int   g_off[NN + 1];     // CSR offsets
__device__ int   g_ocpy[NN];        // running cursor for scatter
__device__ int   g_eid[NE];         // edge ids sorted by row
// pre-transposed fp16 weights: WT[n][k] = (half)W[k][n]
__device__ __align__(16) __half g_W1f[128 * 384];
__device__ __align__(16) __half g_W2f[128 * 128];
__device__ __align__(16) __half g_N1f[128 * 256];
__device__ __align__(16) __half g_N2f[128 * 128];

// ============================= helpers =============================
__device__ __forceinline__ uint32_t smem_to_u32(const void* p) {
    uint32_t a;
    asm("{ .reg .u64 t; cvta.to.shared.u64 t, %1; cvt.u32.u64 %0, t; }" : "=r"(a) : "l"(p));
    return a;
}
__device__ __forceinline__ void ldsm4(uint32_t* r, uint32_t addr) {
    asm volatile("ldmatrix.sync.aligned.m8n8.x4.shared.b16 {%0,%1,%2,%3}, [%4];"
                 : "=r"(r[0]), "=r"(r[1]), "=r"(r[2]), "=r"(r[3]) : "r"(addr));
}
__device__ __forceinline__ void mma16816(float* c, const uint32_t* a,
                                         uint32_t b0, uint32_t b1) {
    asm volatile(
        "mma.sync.aligned.m16n8k16.row.col.f32.f16.f16.f32 "
        "{%0,%1,%2,%3}, {%4,%5,%6,%7}, {%8,%9}, {%0,%1,%2,%3};"
        : "+f"(c[0]), "+f"(c[1]), "+f"(c[2]), "+f"(c[3])
        : "r"(a[0]), "r"(a[1]), "r"(a[2]), "r"(a[3]), "r"(b0), "r"(b1));
}
__device__ __forceinline__ void cpa16(uint32_t dst, const void* src) {
    asm volatile("cp.async.cg.shared.global [%0], [%1], 16;" :: "r"(dst), "l"(src));
}
#define CP_COMMIT asm volatile("cp.async.commit_group;" ::: "memory")
#define CP_WAIT0  asm volatile("cp.async.wait_group 0;"  ::: "memory")
#define CP_WAIT1  asm volatile("cp.async.wait_group 1;"  ::: "memory")

__device__ __forceinline__ uint32_t pack2h(float a, float b) {
    __half2 h2; h2.x = __float2half(a); h2.y = __float2half(b);
    return *reinterpret_cast<uint32_t*>(&h2);
}
__device__ __forceinline__ long long load_idx(const void* ei, long long pos, int is64) {
    return is64 ? ((const long long*)ei)[pos] : (long long)((const int*)ei)[pos];
}

// ============================= SMEM layout (bytes) =============================
#define SM_B1   0            // bias1 [128] f32
#define SM_B2   512          // bias2 [128] f32
#define APB(b)  (4096 + (b) * 18432)     // A fp16 double buffer
#define BPB(b)  (40960 + (b) * 18432)    // B fp16 triple buffer
#define SMEM_TOTAL 96256     // 2 CTAs/SM

// ============================= CSR build kernels =============================
__global__ void detect_kernel(const int* ei32) {
    if (threadIdx.x == 0 && blockIdx.x == 0) {
        int is64 = 1;
        for (int i = 0; i < 128; i++)
            if (ei32[2 * i + 1] != 0) { is64 = 0; break; }
        g_is64 = is64;
    }
}
__global__ void zero_small() {
    int i = blockIdx.x * blockDim.x + threadIdx.x;
    if (i < NN) g_icnt[i] = 0;
}
__global__ void hist_kernel(const void* ei) {
    const int is64 = g_is64;
    int stride = gridDim.x * blockDim.x;
    for (int e = blockIdx.x * blockDim.x + threadIdx.x; e < NE; e += stride)
        atomicAdd(&g_icnt[(int)load_idx(ei, e, is64)], 1);
}
__global__ void scan_kernel() {
    __shared__ int ssum[1024];
    const int t = threadIdx.x;
    const int CH = (NN + 1023) / 1024;
    const int base = t * CH;
    const int lim = min(base + CH, NN);
    int lsum = 0;
    for (int i = base; i < lim; i++) lsum += g_icnt[i];
    ssum[t] = lsum;
    __syncthreads();
    for (int d = 1; d < 1024; d <<= 1) {
        int v = (t >= d) ? ssum[t - d] : 0;
        __syncthreads();
        ssum[t] += v;
        __syncthreads();
    }
    int run = (t == 0) ? 0 : ssum[t - 1];
    for (int i = base; i < lim; i++) {
        g_off[i] = run; g_ocpy[i] = run;
        run += g_icnt[i];
    }
    if (t == 1023) g_off[NN] = NE;
}
__global__ void scatter_kernel(const void* ei) {
    const int is64 = g_is64;
    int stride = gridDim.x * blockDim.x;
    for (int e = blockIdx.x * blockDim.x + threadIdx.x; e < NE; e += stride) {
        int r = (int)load_idx(ei, e, is64);
        int pos = atomicAdd(&g_ocpy[r], 1);
        g_eid[pos] = e;
    }
}
// one warp per node: mean of its edge messages -> g_agg
__global__ void __launch_bounds__(256) agg_kernel(const float* __restrict__ edge_out) {
    const int w = (blockIdx.x * blockDim.x + threadIdx.x) >> 5;
    const int lane = threadIdx.x & 31;
    if (w >= NN) return;
    const int c0 = g_off[w], c1 = g_off[w + 1];
    float4 s = make_float4(0.f, 0.f, 0.f, 0.f);
    for (int i = c0; i < c1; i++) {
        const int e = g_eid[i];
        float4 v = *(const float4*)(edge_out + (size_t)e * 128 + lane * 4);
        s.x += v.x; s.y += v.y; s.z += v.z; s.w += v.w;
    }
    const float inv = 1.0f / (float)max(c1 - c0, 1);
    *(float4*)(g_agg + (size_t)w * 128 + lane * 4) =
        make_float4(s.x * inv, s.y * inv, s.z * inv, s.w * inv);
}

__global__ void prep_kernel(const float* We1, const float* We2,
                            const float* Wn1, const float* Wn2) {
    int i = blockIdx.x * blockDim.x + threadIdx.x;
    if (i < 49152) {
        int k = i / 128, n = i % 128;
        g_W1f[n * 384 + k] = __float2half(We1[i]);
    } else if (i < 65536) {
        int j = i - 49152; int k = j / 128, n = j % 128;
        g_W2f[n * 128 + k] = __float2half(We2[j]);
    } else if (i < 98304) {
        int j = i - 65536; int k = j / 128, n = j % 128;
        g_N1f[n * 256 + k] = __float2half(Wn1[j]);
    } else if (i < 114688) {
        int j = i - 98304; int k = j / 128, n = j % 128;
        g_N2f[n * 128 + k] = __float2half(Wn2[j]);
    }
}

// ============================= GEMM slab (K=64), warp tile 64x32, fp16 1-pass ============
__device__ __forceinline__ void gemm_slab32(
    float acc[4][4][4], uint32_t smb,
    uint32_t aP, uint32_t bP,
    int m0, int n0, int rowA, int kA, int rowB, int kB)
{
    #pragma unroll
    for (int k16 = 0; k16 < 4; k16++) {
        const int kk = k16 * 16;
        uint32_t ah[4][4], bb[2][4];
        #pragma unroll
        for (int mt = 0; mt < 4; mt++)
            ldsm4(ah[mt], smb + aP + (uint32_t)(((m0 + mt * 16 + rowA) * PSTR + kk + kA) * 2));
        #pragma unroll
        for (int np = 0; np < 2; np++)
            ldsm4(bb[np], smb + bP + (uint32_t)(((n0 + np * 16 + rowB) * PSTR + kk + kB) * 2));
        #pragma unroll
        for (int mt = 0; mt < 4; mt++)
            #pragma unroll
            for (int na = 0; na < 4; na++)
                mma16816(acc[mt][na], ah[mt], bb[na >> 1][(na & 1) * 2], bb[na >> 1][(na & 1) * 2 + 1]);
    }
}

// ============================= fused MLP kernel =============================
// CTA: 128 rows x 128 out, 256 thr, 8 warps (2m x 4n), warp tile 64x32, 2 CTAs/SM.
// NO aggregation atomics — scatter-mean handled by CSR agg_kernel.
template <bool IS_EDGE>
__global__ void __launch_bounds__(256, 2) mlp_kernel(
    const float* __restrict__ x, const void* __restrict__ ei,
    const float* __restrict__ ea,
    const float* __restrict__ b1v, const float* __restrict__ b2v,
    float* __restrict__ outp)
{
    extern __shared__ char smc[];
    const uint32_t smb = smem_to_u32(smc);
    const int tid = threadIdx.x;
    const int wid = tid >> 5, lane = tid & 31;
    const long long r0 = (long long)blockIdx.x * 128;
    const int NS = IS_EDGE ? 6 : 4;

    float* sb1 = (float*)(smc + SM_B1);
    float* sb2 = (float*)(smc + SM_B2);

    // thread pair shares row = tid>>1; half index (tid&1): 32 floats each
    const int row = tid >> 1, hfl = (tid & 1) * 32;
    const float* aBase[3];
    if (IS_EDGE) {
        const int is64 = g_is64;
        long long rr = load_idx(ei, r0 + row, is64);
        long long cc = load_idx(ei, (long long)NE + r0 + row, is64);
        aBase[0] = x + (size_t)rr * 128;
        aBase[1] = x + (size_t)cc * 128;
        aBase[2] = ea + (size_t)(r0 + row) * 128;
    } else {
        long long nd = r0 + row; if (nd > NN - 1) nd = NN - 1;
        aBase[0] = x + (size_t)nd * 128;
        aBase[1] = g_agg + (size_t)nd * 128;    // already mean
        aBase[2] = g_agg + (size_t)nd * 128;
    }
    if (tid < 128) { sb1[tid] = b1v[tid]; sb2[tid] = b2v[tid]; }

    // ---- staging helpers ----
    auto ldgA = [&](int s, float4* v) {
        const float* p = aBase[s >> 1] + (s & 1) * 64 + hfl;
        #pragma unroll
        for (int j = 0; j < 8; j++) v[j] = *(const float4*)(p + j * 4);
    };
    auto stsA = [&](int s, const float4* v) {
        const int ob = row * (PSTR * 2) + hfl * 2;
        #pragma unroll
        for (int j = 0; j < 4; j++) {
            uint32_t w0 = pack2h(v[2 * j].x,     v[2 * j].y);
            uint32_t w1 = pack2h(v[2 * j].z,     v[2 * j].w);
            uint32_t w2 = pack2h(v[2 * j + 1].x, v[2 * j + 1].y);
            uint32_t w3 = pack2h(v[2 * j + 1].z, v[2 * j + 1].w);
            *(uint4*)(smc + APB(s & 1) + ob + j * 16) = make_uint4(w0, w1, w2, w3);
        }
    };
    auto stageB = [&](int seq) {
        if (seq > NS + 1) return;
        const __half* wf; int KW, koff;
        if (seq < NS) {
            wf = IS_EDGE ? g_W1f : g_N1f;
            KW = IS_EDGE ? 384 : 256; koff = seq * 64;
        } else {
            wf = IS_EDGE ? g_W2f : g_N2f;
            KW = 128; koff = (seq - NS) * 64;
        }
        const uint32_t dst = smb + BPB(seq % 3)
                           + (uint32_t)(row * (PSTR * 2) + hfl * 2);
        const __half* src = wf + (size_t)row * KW + koff + hfl;
        #pragma unroll
        for (int j = 0; j < 4; j++) cpa16(dst + j * 16, src + j * 8);
    };

    // ---- warp tiling ----
    const int m0 = (wid >> 2) * 64, n0 = (wid & 3) * 32;
    const int rowA = (lane & 7) + 8 * ((lane >> 3) & 1), kA = 8 * (lane >> 4);
    const int rowB = (lane & 7) + 8 * ((lane >> 4) & 1), kB = 8 * ((lane >> 3) & 1);
    const int g = lane >> 2, t4 = lane & 3;

    float acc[4][4][4];
    #pragma unroll
    for (int a = 0; a < 4; a++)
        #pragma unroll
        for (int b = 0; b < 4; b++)
            #pragma unroll
            for (int c = 0; c < 4; c++) acc[a][b][c] = 0.0f;

    // ---- prologue ----
    stageB(0); CP_COMMIT;
    stageB(1); CP_COMMIT;
    {
        float4 v[8];
        ldgA(0, v);
        stsA(0, v);
    }
    CP_WAIT1;
    __syncthreads();

    // ---- GEMM1: single-sync pipeline ----
    for (int s = 0; s < NS; s++) {
        float4 v[8];
        if (s + 1 < NS) ldgA(s + 1, v);
        gemm_slab32(acc, smb, APB(s & 1), BPB(s % 3),
                    m0, n0, rowA, kA, rowB, kB);
        if (s + 1 < NS) stsA(s + 1, v);
        stageB(s + 2); CP_COMMIT;
        CP_WAIT1;
        __syncthreads();
    }

    // ---- hidden: bias+relu -> fp16; cols<64 -> A[0], cols>=64 -> A[1] ----
    #pragma unroll
    for (int mt = 0; mt < 4; mt++) {
        const int r1 = m0 + mt * 16 + g, r2 = r1 + 8;
        #pragma unroll
        for (int na = 0; na < 4; na++) {
            const int c = n0 + na * 8 + 2 * t4;
            float h00 = fmaxf(acc[mt][na][0] + sb1[c],     0.0f);
            float h01 = fmaxf(acc[mt][na][1] + sb1[c + 1], 0.0f);
            float h10 = fmaxf(acc[mt][na][2] + sb1[c],     0.0f);
            float h11 = fmaxf(acc[mt][na][3] + sb1[c + 1], 0.0f);
            const int buf = (c < 64) ? 0 : 1;
            const int cc = c & 63;
            *(uint32_t*)(smc + APB(buf) + (r1 * PSTR + cc) * 2) = pack2h(h00, h01);
            *(uint32_t*)(smc + APB(buf) + (r2 * PSTR + cc) * 2) = pack2h(h10, h11);
            acc[mt][na][0] = acc[mt][na][1] = acc[mt][na][2] = acc[mt][na][3] = 0.0f;
        }
    }
    CP_WAIT0;
    __syncthreads();

    // ---- GEMM2 ----
    gemm_slab32(acc, smb, APB(0), BPB(NS % 3),
                m0, n0, rowA, kA, rowB, kB);
    gemm_slab32(acc, smb, APB(1), BPB((NS + 1) % 3),
                m0, n0, rowA, kA, rowB, kB);

    // ---- epilogue: bias -> store only ----
    #pragma unroll
    for (int mt = 0; mt < 4; mt++) {
        const int r1 = m0 + mt * 16 + g, r2 = r1 + 8;
        #pragma unroll
        for (int na = 0; na < 4; na++) {
            const int c = n0 + na * 8 + 2 * t4;
            const float b0 = sb2[c], b1 = sb2[c + 1];
            float v00 = acc[mt][na][0] + b0, v01 = acc[mt][na][1] + b1;
            float v10 = acc[mt][na][2] + b0, v11 = acc[mt][na][3] + b1;
            if (IS_EDGE) {
                *(float2*)(outp + (size_t)(r0 + r1) * 128 + c) = make_float2(v00, v01);
                *(float2*)(outp + (size_t)(r0 + r2) * 128 + c) = make_float2(v10, v11);
            } else {
                if (r0 + r1 < NN)
                    *(float2*)(outp + (size_t)(r0 + r1) * 128 + c) = make_float2(v00, v01);
                if (r0 + r2 < NN)
                    *(float2*)(outp + (size_t)(r0 + r2) * 128 + c) = make_float2(v10, v11);
            }
        }
    }
}

// ============================= launch =============================
extern "C" void kernel_launch(void* const* d_in, const int* in_sizes, int n_in,
                              void* d_out, int out_size) {
    const float* x   = (const float*)d_in[0];
    const void*  ei  = d_in[1];
    const float* ea  = (const float*)d_in[2];
    const float* be1 = (const float*)d_in[4];
    const float* be2 = (const float*)d_in[6];
    const float* bn1 = (const float*)d_in[8];
    const float* bn2 = (const float*)d_in[10];

    float* out      = (float*)d_out;
    float* x_out    = out;                       // [NN, 128]
    float* edge_out = out + (size_t)NN * 128;    // [NE, 128]

    cudaFuncSetAttribute(mlp_kernel<true>,  cudaFuncAttributeMaxDynamicSharedMemorySize, SMEM_TOTAL);
    cudaFuncSetAttribute(mlp_kernel<false>, cudaFuncAttributeMaxDynamicSharedMemorySize, SMEM_TOTAL);

    detect_kernel<<<1, 32>>>((const int*)ei);
    zero_small<<<(NN + 255) / 256, 256>>>();
    prep_kernel<<<448, 256>>>((const float*)d_in[3], (const float*)d_in[5],
                              (const float*)d_in[7], (const float*)d_in[9]);
    hist_kernel<<<512, 256>>>(ei);
    scan_kernel<<<1, 1024>>>();
    scatter_kernel<<<512, 256>>>(ei);
    mlp_kernel<true><<<NE / 128, 256, SMEM_TOTAL>>>(x, ei, ea, be1, be2, edge_out);
    agg_kernel<<<(NN * 32 + 255) / 256, 256>>>(edge_out);
    mlp_kernel<false><<<(NN + 127) / 128, 256, SMEM_TOTAL>>>(x, ei, ea, bn1, bn2, x_out);
}